// round 5
// baseline (speedup 1.0000x reference)
#include <cuda_runtime.h>

// Problem constants (fixed by the reference):
//   x: [B, 96, 128, 128] fp32, depthwise 3x3, stride 1, pad 1
#define C_DIM 96
#define HW 128
#define PLANE (HW * HW)          // 16384
#define CR 24                    // C_DIM / 4
#define BN_EPS 1e-5f
#define MAX_B 64

// Scratch (allocation-free rule: __device__ global)
__device__ float g_pooled[MAX_B * C_DIM];

// ---------------------------------------------------------------------------
// Kernel 1: global average pool over each (b,c) plane.
// One block per plane, 256 threads, float4 loads.  (measured 80% DRAM — keep)
// ---------------------------------------------------------------------------
__global__ __launch_bounds__(256) void pool_kernel(const float* __restrict__ x,
                                                   float* __restrict__ pooled) {
    const int plane = blockIdx.x;
    const float4* xp = reinterpret_cast<const float4*>(x + (size_t)plane * PLANE);
    float s = 0.f;
#pragma unroll 4
    for (int i = threadIdx.x; i < PLANE / 4; i += 256) {
        float4 v = xp[i];
        s += (v.x + v.y) + (v.z + v.w);
    }
#pragma unroll
    for (int o = 16; o > 0; o >>= 1) s += __shfl_xor_sync(0xffffffffu, s, o);

    __shared__ float ws[8];
    if ((threadIdx.x & 31) == 0) ws[threadIdx.x >> 5] = s;
    __syncthreads();
    if (threadIdx.x < 8) {
        float t = ws[threadIdx.x];
#pragma unroll
        for (int o = 4; o > 0; o >>= 1) t += __shfl_xor_sync(0xffu, t, o);
        if (threadIdx.x == 0) pooled[plane] = t * (1.f / (float)PLANE);
    }
}

// ---------------------------------------------------------------------------
// Kernel 2 (fused into dwconv): per-sample depthwise 3x3 conv, pad 1, stride 1.
// One block per (b,c) plane; block (32,4): warp s handles rows [32s, 32s+32).
// Register sliding window + shfl for column halos; 4 rows per loop step so
// 4 LDG.128s are front-batched (MLP_p1=4). The block also recomputes its
// sample's h1 and its channel's 9 dynamic weights (cheap, hides under DRAM).
// ---------------------------------------------------------------------------
#define STRIPS 4
#define SROWS (HW / STRIPS)   // 32

struct Row { float4 v; float l, r; };

__device__ __forceinline__ Row mkrow(float4 v, int lane) {
    Row rr; rr.v = v;
    float l = __shfl_up_sync(0xffffffffu, v.w, 1);
    float r = __shfl_down_sync(0xffffffffu, v.x, 1);
    rr.l = (lane == 0) ? 0.f : l;
    rr.r = (lane == 31) ? 0.f : r;
    return rr;
}

__global__ __launch_bounds__(32 * STRIPS) void dwconv_kernel(
    const float* __restrict__ x,
    const float* __restrict__ pooled,
    const float* __restrict__ w1,      // [CR, C_DIM]
    const float* __restrict__ gamma,
    const float* __restrict__ beta,
    const float* __restrict__ rmean,
    const float* __restrict__ rvar,
    const float* __restrict__ w2,      // [C_DIM*9, CR]
    const float* __restrict__ b2,
    const float* __restrict__ bias,
    float* __restrict__ out) {
    const int plane = blockIdx.x;          // b*C + c
    const int b  = plane / C_DIM;
    const int ch = plane % C_DIM;
    const int lane = threadIdx.x;
    const int row0 = threadIdx.y * SROWS;
    const int tid = threadIdx.y * 32 + threadIdx.x;

    const float* xp = x + (size_t)plane * PLANE;
    float* op = out + (size_t)plane * PLANE;

    // Issue prologue row loads FIRST — DRAM latency hides under weight math.
    auto loadrow = [&](int r) -> float4 {
        if ((unsigned)r < (unsigned)HW)
            return reinterpret_cast<const float4*>(xp + r * HW)[lane];
        return make_float4(0.f, 0.f, 0.f, 0.f);
    };
    float4 va = loadrow(row0 - 1);
    float4 vb = loadrow(row0);

    // ---- fused dynamic-weight computation (this block's channel only) ----
    __shared__ float sp[C_DIM];
    __shared__ float sh1[CR];
    __shared__ float sw[12];
    if (tid < C_DIM) sp[tid] = pooled[b * C_DIM + tid];
    __syncthreads();
    if (tid < CR) {
        float s = 0.f;
        const float* wr = w1 + tid * C_DIM;
#pragma unroll 8
        for (int c = 0; c < C_DIM; c++) s += sp[c] * __ldg(wr + c);
        s = (s - __ldg(rmean + tid)) * rsqrtf(__ldg(rvar + tid) + BN_EPS) * __ldg(gamma + tid) + __ldg(beta + tid);
        sh1[tid] = 1.f / (1.f + __expf(-s));
    }
    __syncthreads();
    if (tid < 9) {
        const int o = ch * 9 + tid;
        float s = __ldg(b2 + o);
        const float* wr = w2 + (size_t)o * CR;
#pragma unroll
        for (int j = 0; j < CR; j++) s += sh1[j] * __ldg(wr + j);
        sw[tid] = s;
    }
    __syncthreads();

    float w[9];
#pragma unroll
    for (int i = 0; i < 9; i++) w[i] = sw[i];
    const float bv = __ldg(bias + ch);

    // ---- conv main loop: 4 rows per step, front-batched loads ----
    Row A = mkrow(va, lane);
    Row B = mkrow(vb, lane);

    auto emit = [&](int r, const Row& T, const Row& M, const Row& D) {
        float a0 = bv, a1 = bv, a2 = bv, a3 = bv;
#pragma unroll
        for (int dy = 0; dy < 3; dy++) {
            const Row& R = (dy == 0) ? T : (dy == 1) ? M : D;
            const float w0 = w[dy * 3 + 0], w1_ = w[dy * 3 + 1], w2_ = w[dy * 3 + 2];
            a0 += R.l   * w0 + R.v.x * w1_ + R.v.y * w2_;
            a1 += R.v.x * w0 + R.v.y * w1_ + R.v.z * w2_;
            a2 += R.v.y * w0 + R.v.z * w1_ + R.v.w * w2_;
            a3 += R.v.z * w0 + R.v.w * w1_ + R.r   * w2_;
        }
        float4 o; o.x = a0; o.y = a1; o.z = a2; o.w = a3;
        reinterpret_cast<float4*>(op + (row0 + r) * HW)[lane] = o;
    };

#pragma unroll 2
    for (int i = 0; i < SROWS; i += 4) {
        // 4 independent loads batched up front (MLP_p1 = 4)
        float4 n0 = loadrow(row0 + i + 1);
        float4 n1 = loadrow(row0 + i + 2);
        float4 n2 = loadrow(row0 + i + 3);
        float4 n3 = loadrow(row0 + i + 4);

        Row C0 = mkrow(n0, lane); emit(i + 0, A,  B,  C0);
        Row C1 = mkrow(n1, lane); emit(i + 1, B,  C0, C1);
        Row C2 = mkrow(n2, lane); emit(i + 2, C0, C1, C2);
        Row C3 = mkrow(n3, lane); emit(i + 3, C1, C2, C3);

        A = C2; B = C3;
    }
}

// ---------------------------------------------------------------------------
// Launch
// ---------------------------------------------------------------------------
extern "C" void kernel_launch(void* const* d_in, const int* in_sizes, int n_in,
                              void* d_out, int out_size) {
    const float* x     = (const float*)d_in[0];
    const float* w1    = (const float*)d_in[1];
    const float* gamma = (const float*)d_in[2];
    const float* beta  = (const float*)d_in[3];
    const float* rmean = (const float*)d_in[4];
    const float* rvar  = (const float*)d_in[5];
    const float* w2    = (const float*)d_in[6];
    const float* b2    = (const float*)d_in[7];
    const float* bias  = (const float*)d_in[8];
    float* out = (float*)d_out;

    const int B = in_sizes[0] / (C_DIM * PLANE);
    const int planes = B * C_DIM;

    float* pooled;
    cudaGetSymbolAddress((void**)&pooled, g_pooled);

    pool_kernel<<<planes, 256>>>(x, pooled);
    dim3 block(32, STRIPS);
    dwconv_kernel<<<planes, block>>>(x, pooled, w1, gamma, beta, rmean, rvar,
                                     w2, b2, bias, out);
}

// round 8
// speedup vs baseline: 1.1165x; 1.1165x over previous
#include <cuda_runtime.h>

// Problem constants (fixed by the reference):
//   x: [B, 96, 128, 128] fp32, depthwise 3x3, stride 1, pad 1
#define C_DIM 96
#define HW 128
#define PLANE (HW * HW)          // 16384
#define CR 24                    // C_DIM / 4
#define WDYN_PER_B (C_DIM * 9)   // 864
#define BN_EPS 1e-5f
#define MAX_B 64

// Scratch (allocation-free rule: __device__ globals)
__device__ float g_pooled[MAX_B * C_DIM];
__device__ float g_wdyn[MAX_B * WDYN_PER_B];

// ---------------------------------------------------------------------------
// Kernel 1: global average pool over each (b,c) plane.
// One block per plane, 256 threads, float4 loads.  (measured 80% DRAM — keep)
// ---------------------------------------------------------------------------
__global__ __launch_bounds__(256) void pool_kernel(const float* __restrict__ x,
                                                   float* __restrict__ pooled) {
    const int plane = blockIdx.x;
    const float4* xp = reinterpret_cast<const float4*>(x + (size_t)plane * PLANE);
    float s = 0.f;
#pragma unroll 4
    for (int i = threadIdx.x; i < PLANE / 4; i += 256) {
        float4 v = xp[i];
        s += (v.x + v.y) + (v.z + v.w);
    }
#pragma unroll
    for (int o = 16; o > 0; o >>= 1) s += __shfl_xor_sync(0xffffffffu, s, o);

    __shared__ float ws[8];
    if ((threadIdx.x & 31) == 0) ws[threadIdx.x >> 5] = s;
    __syncthreads();
    if (threadIdx.x < 8) {
        float t = ws[threadIdx.x];
#pragma unroll
        for (int o = 4; o > 0; o >>= 1) t += __shfl_xor_sync(0xffu, t, o);
        if (threadIdx.x == 0) pooled[plane] = t * (1.f / (float)PLANE);
    }
}

// ---------------------------------------------------------------------------
// Kernel 2: dynamic weight generation. One block per batch sample. (tiny)
// ---------------------------------------------------------------------------
__global__ __launch_bounds__(256) void weight_kernel(
    const float* __restrict__ pooled,
    const float* __restrict__ w1,      // [CR, C_DIM]
    const float* __restrict__ gamma,
    const float* __restrict__ beta,
    const float* __restrict__ rmean,
    const float* __restrict__ rvar,
    const float* __restrict__ w2,      // [WDYN_PER_B, CR]
    const float* __restrict__ b2,
    float* __restrict__ wdyn) {
    const int b = blockIdx.x;
    __shared__ float p[C_DIM];
    __shared__ float h1[CR];
    const int tid = threadIdx.x;

    if (tid < C_DIM) p[tid] = pooled[b * C_DIM + tid];
    __syncthreads();

    if (tid < CR) {
        float s = 0.f;
        const float* wr = w1 + tid * C_DIM;
#pragma unroll 8
        for (int c = 0; c < C_DIM; c++) s += p[c] * wr[c];
        s = (s - rmean[tid]) * rsqrtf(rvar[tid] + BN_EPS) * gamma[tid] + beta[tid];
        h1[tid] = 1.f / (1.f + __expf(-s));
    }
    __syncthreads();

    for (int o = tid; o < WDYN_PER_B; o += 256) {
        float s = b2[o];
        const float* wr = w2 + o * CR;
#pragma unroll
        for (int j = 0; j < CR; j++) s += h1[j] * wr[j];
        wdyn[b * WDYN_PER_B + o] = s;
    }
}

// ---------------------------------------------------------------------------
// Kernel 3: per-sample depthwise 3x3 conv, pad 1, stride 1 — smem tile.
// Grid (planes, 4); block (32,8) = 256 threads, ~30 regs, 18.5KB smem
//   -> 8 CTAs/SM = 64 warps = 100% occupancy (warp-capped).
// Tile: 34 rows x 136 cols; tile col 0 maps to x col -1 (zero halo).
// Halo read amplification only 34/32 = 6%. Each thread: 4 output rows x 4 cols.
// ---------------------------------------------------------------------------
#define ROWS 32
#define TROWS (ROWS + 2)   // 34
#define TW 136             // 130 used, padded

__global__ __launch_bounds__(256) void dwconv_kernel(
    const float* __restrict__ x,
    const float* __restrict__ wdyn,
    const float* __restrict__ bias,
    float* __restrict__ out) {
    const int plane = blockIdx.x;          // b*C + c
    const int ch = plane % C_DIM;
    const int row0 = blockIdx.y * ROWS;

    __shared__ float tile[TROWS][TW];

    const float* xp = x + (size_t)plane * PLANE;
    float* op = out + (size_t)plane * PLANE;

    const int tid = threadIdx.y * 32 + threadIdx.x;

    // ---- load phase: 34 rows x 32 float4, front-batched 4-deep + tail ----
    {
        float4 v[4];
        int rr[4], cc[4];
#pragma unroll
        for (int k = 0; k < 4; k++) {
            const int i = tid + k * 256;           // 0..1023
            rr[k] = i >> 5;
            cc[k] = i & 31;
            const int gr = row0 - 1 + rr[k];
            v[k] = make_float4(0.f, 0.f, 0.f, 0.f);
            if ((unsigned)gr < (unsigned)HW)
                v[k] = *reinterpret_cast<const float4*>(xp + gr * HW + cc[k] * 4);
        }
#pragma unroll
        for (int k = 0; k < 4; k++) {
            float* t = &tile[rr[k]][1 + cc[k] * 4];
            t[0] = v[k].x; t[1] = v[k].y; t[2] = v[k].z; t[3] = v[k].w;
        }
        // tail: indices 1024..1087 (rows 32,33)
        if (tid < TROWS * 32 - 1024) {
            const int i = tid + 1024;
            const int r = i >> 5, cq = i & 31;
            const int gr = row0 - 1 + r;
            float4 tv = make_float4(0.f, 0.f, 0.f, 0.f);
            if ((unsigned)gr < (unsigned)HW)
                tv = *reinterpret_cast<const float4*>(xp + gr * HW + cq * 4);
            float* t = &tile[r][1 + cq * 4];
            t[0] = tv.x; t[1] = tv.y; t[2] = tv.z; t[3] = tv.w;
        }
        // zero column halos (x col -1 -> tile col 0, x col 128 -> tile col 129)
        if (tid < 2 * TROWS) {
            const int r = tid >> 1;
            tile[r][(tid & 1) ? 129 : 0] = 0.f;
        }
    }

    // per-channel dynamic 3x3 weights (broadcast, L1-cached) — overlap w/ loads
    float w[9];
    const float* wp = wdyn + (size_t)plane * 9;
#pragma unroll
    for (int i = 0; i < 9; i++) w[i] = __ldg(wp + i);
    const float bv = __ldg(bias + ch);

    __syncthreads();

    // ---- compute phase: thread -> output rows 4*ty..4*ty+3, cols 4*tx.. ----
    const int cx = threadIdx.x * 4;
#pragma unroll
    for (int j = 0; j < 4; j++) {
        const int rt = threadIdx.y * 4 + j;   // output row within tile
        float a0 = bv, a1 = bv, a2 = bv, a3 = bv;
#pragma unroll
        for (int dy = 0; dy < 3; dy++) {
            const float4 v0 = *reinterpret_cast<const float4*>(&tile[rt + dy][cx]);
            const float2 v1 = *reinterpret_cast<const float2*>(&tile[rt + dy][cx + 4]);
            const float w0 = w[dy * 3 + 0], w1_ = w[dy * 3 + 1], w2_ = w[dy * 3 + 2];
            a0 += v0.x * w0 + v0.y * w1_ + v0.z * w2_;
            a1 += v0.y * w0 + v0.z * w1_ + v0.w * w2_;
            a2 += v0.z * w0 + v0.w * w1_ + v1.x * w2_;
            a3 += v0.w * w0 + v1.x * w1_ + v1.y * w2_;
        }
        float4 o; o.x = a0; o.y = a1; o.z = a2; o.w = a3;
        *reinterpret_cast<float4*>(op + (row0 + rt) * HW + cx) = o;
    }
}

// ---------------------------------------------------------------------------
// Launch
// ---------------------------------------------------------------------------
extern "C" void kernel_launch(void* const* d_in, const int* in_sizes, int n_in,
                              void* d_out, int out_size) {
    const float* x     = (const float*)d_in[0];
    const float* w1    = (const float*)d_in[1];
    const float* gamma = (const float*)d_in[2];
    const float* beta  = (const float*)d_in[3];
    const float* rmean = (const float*)d_in[4];
    const float* rvar  = (const float*)d_in[5];
    const float* w2    = (const float*)d_in[6];
    const float* b2    = (const float*)d_in[7];
    const float* bias  = (const float*)d_in[8];
    float* out = (float*)d_out;

    const int B = in_sizes[0] / (C_DIM * PLANE);
    const int planes = B * C_DIM;

    float* pooled;
    float* wdyn;
    cudaGetSymbolAddress((void**)&pooled, g_pooled);
    cudaGetSymbolAddress((void**)&wdyn, g_wdyn);

    pool_kernel<<<planes, 256>>>(x, pooled);
    weight_kernel<<<B, 256>>>(pooled, w1, gamma, beta, rmean, rvar, w2, b2, wdyn);
    dim3 grid(planes, HW / ROWS);
    dim3 block(32, 8);
    dwconv_kernel<<<grid, block>>>(x, wdyn, bias, out);
}

// round 9
// speedup vs baseline: 1.1638x; 1.0424x over previous
#include <cuda_runtime.h>

// Problem constants (fixed by the reference):
//   x: [B, 96, 128, 128] fp32, depthwise 3x3, stride 1, pad 1
#define C_DIM 96
#define HW 128
#define PLANE (HW * HW)          // 16384
#define CR 24                    // C_DIM / 4
#define WDYN_PER_B (C_DIM * 9)   // 864
#define BN_EPS 1e-5f
#define MAX_B 64

// Scratch (allocation-free rule: __device__ globals)
__device__ float g_pooled[MAX_B * C_DIM];
__device__ float g_wdyn[MAX_B * WDYN_PER_B];

// ---------------------------------------------------------------------------
// Kernel 1: global average pool over each (b,c) plane. (80.9% DRAM — keep)
// ---------------------------------------------------------------------------
__global__ __launch_bounds__(256) void pool_kernel(const float* __restrict__ x,
                                                   float* __restrict__ pooled) {
    const int plane = blockIdx.x;
    const float4* xp = reinterpret_cast<const float4*>(x + (size_t)plane * PLANE);
    float s = 0.f;
#pragma unroll 4
    for (int i = threadIdx.x; i < PLANE / 4; i += 256) {
        float4 v = xp[i];
        s += (v.x + v.y) + (v.z + v.w);
    }
#pragma unroll
    for (int o = 16; o > 0; o >>= 1) s += __shfl_xor_sync(0xffffffffu, s, o);

    __shared__ float ws[8];
    if ((threadIdx.x & 31) == 0) ws[threadIdx.x >> 5] = s;
    __syncthreads();
    if (threadIdx.x < 8) {
        float t = ws[threadIdx.x];
#pragma unroll
        for (int o = 4; o > 0; o >>= 1) t += __shfl_xor_sync(0xffu, t, o);
        if (threadIdx.x == 0) pooled[plane] = t * (1.f / (float)PLANE);
    }
}

// ---------------------------------------------------------------------------
// Kernel 2: dynamic weight generation. One block per batch sample. (tiny)
// ---------------------------------------------------------------------------
__global__ __launch_bounds__(256) void weight_kernel(
    const float* __restrict__ pooled,
    const float* __restrict__ w1,      // [CR, C_DIM]
    const float* __restrict__ gamma,
    const float* __restrict__ beta,
    const float* __restrict__ rmean,
    const float* __restrict__ rvar,
    const float* __restrict__ w2,      // [WDYN_PER_B, CR]
    const float* __restrict__ b2,
    float* __restrict__ wdyn) {
    const int b = blockIdx.x;
    __shared__ float p[C_DIM];
    __shared__ float h1[CR];
    const int tid = threadIdx.x;

    if (tid < C_DIM) p[tid] = pooled[b * C_DIM + tid];
    __syncthreads();

    if (tid < CR) {
        float s = 0.f;
        const float* wr = w1 + tid * C_DIM;
#pragma unroll 8
        for (int c = 0; c < C_DIM; c++) s += p[c] * wr[c];
        s = (s - rmean[tid]) * rsqrtf(rvar[tid] + BN_EPS) * gamma[tid] + beta[tid];
        h1[tid] = 1.f / (1.f + __expf(-s));
    }
    __syncthreads();

    for (int o = tid; o < WDYN_PER_B; o += 256) {
        float s = b2[o];
        const float* wr = w2 + o * CR;
#pragma unroll
        for (int j = 0; j < CR; j++) s += h1[j] * wr[j];
        wdyn[b * WDYN_PER_B + o] = s;
    }
}

// ---------------------------------------------------------------------------
// Kernel 3: per-sample depthwise 3x3 conv — cp.async double-buffered pipeline.
// One block per plane; 4 tiles of 32 rows, 2 smem buffers. While tile t is
// computed, tile t+1's cp.async loads are in flight -> per-CTA load stream
// never stalls on compute. Column halos (zero pad) via 2 shfls per row.
// Block (32,8)=256 thr; smem 2*34*132*4 ~ 36KB -> 6 CTAs/SM = 48 warps.
// ---------------------------------------------------------------------------
#define ROWS 32
#define TROWS (ROWS + 2)   // 34
#define TW 132             // 128 data cols + pad (row stride 528B, 16B-aligned)

__device__ __forceinline__ void cp16(float* dst, const float* src) {
    unsigned d = (unsigned)__cvta_generic_to_shared(dst);
    asm volatile("cp.async.cg.shared.global [%0], [%1], 16;" :: "r"(d), "l"(src) : "memory");
}
#define CP_COMMIT() asm volatile("cp.async.commit_group;" ::: "memory")
#define CP_WAIT(n)  asm volatile("cp.async.wait_group %0;" :: "n"(n) : "memory")

__global__ __launch_bounds__(256) void dwconv_kernel(
    const float* __restrict__ x,
    const float* __restrict__ wdyn,
    const float* __restrict__ bias,
    float* __restrict__ out) {
    const int plane = blockIdx.x;          // b*C + c
    const int ch = plane % C_DIM;
    const int tid = threadIdx.y * 32 + threadIdx.x;
    const int lane = threadIdx.x;

    __shared__ float tile[2][TROWS][TW];

    const float* xp = x + (size_t)plane * PLANE;
    float* op = out + (size_t)plane * PLANE;

    // tile r (0..33) of a tile starting at output row row0 holds x row row0-1+r
    auto fill = [&](int buf, int row0) {
#pragma unroll
        for (int k = 0; k < 4; k++) {
            const int i = tid + k * 256;          // 0..1023
            const int r = i >> 5, cq = i & 31;
            const int gr = row0 - 1 + r;
            float* dst = &tile[buf][r][cq * 4];
            if ((unsigned)gr < (unsigned)HW)
                cp16(dst, xp + gr * HW + cq * 4);
            else
                *reinterpret_cast<float4*>(dst) = make_float4(0.f, 0.f, 0.f, 0.f);
        }
        if (tid < TROWS * 32 - 1024) {            // rows 32,33
            const int i = tid + 1024;
            const int r = i >> 5, cq = i & 31;
            const int gr = row0 - 1 + r;
            float* dst = &tile[buf][r][cq * 4];
            if ((unsigned)gr < (unsigned)HW)
                cp16(dst, xp + gr * HW + cq * 4);
            else
                *reinterpret_cast<float4*>(dst) = make_float4(0.f, 0.f, 0.f, 0.f);
        }
    };

    // kick off first tile's loads before touching weights
    fill(0, 0);
    CP_COMMIT();

    // per-channel dynamic 3x3 weights (broadcast, hides under cp.asyncs)
    float w[9];
    const float* wp = wdyn + (size_t)plane * 9;
#pragma unroll
    for (int i = 0; i < 9; i++) w[i] = __ldg(wp + i);
    const float bv = __ldg(bias + ch);

    fill(1, ROWS);
    CP_COMMIT();

    const int cx = threadIdx.x * 4;

    auto compute = [&](int buf, int row0) {
#pragma unroll
        for (int j = 0; j < 4; j++) {
            const int rt = threadIdx.y * 4 + j;   // output row within tile
            float a0 = bv, a1 = bv, a2 = bv, a3 = bv;
#pragma unroll
            for (int dy = 0; dy < 3; dy++) {
                const float4 v = *reinterpret_cast<const float4*>(&tile[buf][rt + dy][cx]);
                float vl = __shfl_up_sync(0xffffffffu, v.w, 1);
                float vr = __shfl_down_sync(0xffffffffu, v.x, 1);
                if (lane == 0)  vl = 0.f;   // x col -1 (zero pad)
                if (lane == 31) vr = 0.f;   // x col 128 (zero pad)
                const float w0 = w[dy * 3 + 0], w1_ = w[dy * 3 + 1], w2_ = w[dy * 3 + 2];
                a0 += vl  * w0 + v.x * w1_ + v.y * w2_;
                a1 += v.x * w0 + v.y * w1_ + v.z * w2_;
                a2 += v.y * w0 + v.z * w1_ + v.w * w2_;
                a3 += v.z * w0 + v.w * w1_ + vr  * w2_;
            }
            float4 o; o.x = a0; o.y = a1; o.z = a2; o.w = a3;
            __stcs(reinterpret_cast<float4*>(op + (row0 + rt) * HW + cx), o);
        }
    };

    // tile 0
    CP_WAIT(1); __syncthreads();
    compute(0, 0);
    __syncthreads();
    fill(0, 2 * ROWS); CP_COMMIT();
    // tile 1
    CP_WAIT(1); __syncthreads();
    compute(1, ROWS);
    __syncthreads();
    fill(1, 3 * ROWS); CP_COMMIT();
    // tile 2
    CP_WAIT(1); __syncthreads();
    compute(0, 2 * ROWS);
    __syncthreads();
    // tile 3
    CP_WAIT(0); __syncthreads();
    compute(1, 3 * ROWS);
}

// ---------------------------------------------------------------------------
// Launch
// ---------------------------------------------------------------------------
extern "C" void kernel_launch(void* const* d_in, const int* in_sizes, int n_in,
                              void* d_out, int out_size) {
    const float* x     = (const float*)d_in[0];
    const float* w1    = (const float*)d_in[1];
    const float* gamma = (const float*)d_in[2];
    const float* beta  = (const float*)d_in[3];
    const float* rmean = (const float*)d_in[4];
    const float* rvar  = (const float*)d_in[5];
    const float* w2    = (const float*)d_in[6];
    const float* b2    = (const float*)d_in[7];
    const float* bias  = (const float*)d_in[8];
    float* out = (float*)d_out;

    const int B = in_sizes[0] / (C_DIM * PLANE);
    const int planes = B * C_DIM;

    float* pooled;
    float* wdyn;
    cudaGetSymbolAddress((void**)&pooled, g_pooled);
    cudaGetSymbolAddress((void**)&wdyn, g_wdyn);

    pool_kernel<<<planes, 256>>>(x, pooled);
    weight_kernel<<<B, 256>>>(pooled, w1, gamma, beta, rmean, rvar, w2, b2, wdyn);
    dim3 block(32, 8);
    dwconv_kernel<<<planes, block>>>(x, wdyn, bias, out);
}